// round 11
// baseline (speedup 1.0000x reference)
#include <cuda_runtime.h>
#include <cuda_bf16.h>
#include <cstdint>

// PairwiseRepresentation: masked periodic pairwise distances.
//   positions      [B,N,3]   f32
//   neighbors      [B,N,K]   i32
//   neighbor_mask  [B,N,K]   f32
//   cell           [B,3,3]   f32
//   cell_offsets   [B,N,K,3] f32
//   out            [B,N,K]   f32
//
// R11: table repacked as xy-float2[N] (32KB) + z-float[N] (16KB) — same 48KB,
// but each neighbor gather is LDS.64+LDS.32 (2 instrs) instead of 3x LDS.32:
// -33% LDS instruction count against the L1TEX(53%)/issue(41.5%) residual
// under DRAM. Everything else frozen from R10 (512 thr, 2 CTAs/SM, one-wave
// grid, division-free fill, LDG.128 .cs streams, 4 pairs/lane).

// ---------------- main kernel: packed SoA smem table ----------------
__global__ __launch_bounds__(512, 2)
void pairwise_soa_kernel(const float*  __restrict__ positions,
                         const int*    __restrict__ neighbors,
                         const float*  __restrict__ mask,
                         const float*  __restrict__ cell,
                         const float*  __restrict__ offsets,
                         float*        __restrict__ out,
                         int N, int K, int rowsPer)
{
    extern __shared__ float s_raw[];
    float2* sxy = (float2*)s_raw;        // N float2 (xy), 8B each
    float*  sz  = s_raw + 2 * N;         // N floats (z)

    const int b = blockIdx.y;

    // Division-free fill. Group g = 4 rows = 12 floats = 3 float4 reads.
    //   xy quads: (x0,y0,x1,y1) and (x2,y2,x3,y3)  -> 2 STS.128
    //   z  quad : (z0,z1,z2,z3)                     -> 1 STS.128
    {
        const float4* pb4 = (const float4*)(positions + (size_t)b * N * 3);
        const int nGroups = N >> 2;            // fast path requires N % 4 == 0
        for (int g = threadIdx.x; g < nGroups; g += blockDim.x) {
            const float4 v0 = __ldg(&pb4[3 * g + 0]);  // x0 y0 z0 x1
            const float4 v1 = __ldg(&pb4[3 * g + 1]);  // y1 z1 x2 y2
            const float4 v2 = __ldg(&pb4[3 * g + 2]);  // z2 x3 y3 z3
            *(float4*)(sxy + 4 * g)     = make_float4(v0.x, v0.y, v0.w, v1.x);
            *(float4*)(sxy + 4 * g + 2) = make_float4(v1.z, v1.w, v2.y, v2.z);
            *(float4*)(sz + 4 * g)      = make_float4(v0.z, v1.y, v2.x, v2.w);
        }
        for (int r = (nGroups << 2) + threadIdx.x; r < N; r += blockDim.x) {
            const float* p = positions + (size_t)b * N * 3 + (size_t)r * 3;
            sxy[r] = make_float2(__ldg(&p[0]), __ldg(&p[1]));
            sz[r]  = __ldg(&p[2]);
        }
    }

    // Per-batch cell matrix -> registers.
    const float* cbp = cell + b * 9;
    const float c00 = __ldg(&cbp[0]), c01 = __ldg(&cbp[1]), c02 = __ldg(&cbp[2]);
    const float c10 = __ldg(&cbp[3]), c11 = __ldg(&cbp[4]), c12 = __ldg(&cbp[5]);
    const float c20 = __ldg(&cbp[6]), c21 = __ldg(&cbp[7]), c22 = __ldg(&cbp[8]);

    __syncthreads();

    const int warp    = threadIdx.x >> 5;      // 0..15
    const int lane    = threadIdx.x & 31;
    const int n_warps = blockDim.x >> 5;       // 16

    const int r0 = blockIdx.x * rowsPer;
    const int r1 = min(r0 + rowsPer, N);

    for (int r = r0 + warp; r < r1; r += n_warps) {
        const float2 pixy = sxy[r];
        const float  piz  = sz[r];

        for (int k0 = lane * 4; k0 < K; k0 += 128) {
            const long base = ((long)b * N + r) * (long)K + k0;

            const int4   nb4 = __ldcs((const int4*)  (neighbors + base));
            const float4 mk4 = __ldcs((const float4*)(mask      + base));

            const float* offp = offsets + base * 3;
            const float4 o0 = __ldcs((const float4*)(offp + 0));
            const float4 o1 = __ldcs((const float4*)(offp + 4));
            const float4 o2 = __ldcs((const float4*)(offp + 8));

            const int   jj[4] = { nb4.x, nb4.y, nb4.z, nb4.w };
            const float ox[4] = { o0.x, o0.w, o1.z, o2.y };
            const float oy[4] = { o0.y, o1.x, o1.w, o2.z };
            const float oz[4] = { o0.z, o1.y, o2.x, o2.w };
            const float mm[4] = { mk4.x, mk4.y, mk4.z, mk4.w };

            // Packed gathers: LDS.64 (xy) + LDS.32 (z) per neighbor.
            float2 gxy[4];
            float  gz[4];
#pragma unroll
            for (int t = 0; t < 4; ++t) {
                gxy[t] = sxy[jj[t]];
                gz[t]  = sz[jj[t]];
            }

            float res[4];
#pragma unroll
            for (int t = 0; t < 4; ++t) {
                float dx = gxy[t].x - pixy.x;
                float dy = gxy[t].y - pixy.y;
                float dz = gz[t]    - piz;
                dx = fmaf(ox[t], c00, fmaf(oy[t], c10, fmaf(oz[t], c20, dx)));
                dy = fmaf(ox[t], c01, fmaf(oy[t], c11, fmaf(oz[t], c21, dy)));
                dz = fmaf(ox[t], c02, fmaf(oy[t], c12, fmaf(oz[t], c22, dz)));
                res[t] = (mm[t] > 0.0f)
                       ? sqrtf(fmaf(dx, dx, fmaf(dy, dy, dz * dz))) : 0.0f;
            }

            __stcs((float4*)(out + base),
                   make_float4(res[0], res[1], res[2], res[3]));
        }
    }
}

// ---------------- scalar fallback (oversized N or K%4 != 0) ----------------
__global__ __launch_bounds__(256)
void pairwise_fallback_kernel(const float* __restrict__ positions,
                              const int*   __restrict__ neighbors,
                              const float* __restrict__ mask,
                              const float* __restrict__ cell,
                              const float* __restrict__ offsets,
                              float*       __restrict__ out,
                              int N, int K, long total)
{
    long idx = (long)blockIdx.x * blockDim.x + threadIdx.x;
    if (idx >= total) return;
    const long row = idx / K;
    const int  b   = (int)(row / N);

    const float pix = positions[row * 3 + 0];
    const float piy = positions[row * 3 + 1];
    const float piz = positions[row * 3 + 2];
    const int j = neighbors[idx];
    const float* pj  = positions + ((size_t)b * N + j) * 3;
    const float* cbp = cell + b * 9;
    const float* op  = offsets + idx * 3;
    float dx = pj[0] - pix, dy = pj[1] - piy, dz = pj[2] - piz;
    dx = fmaf(op[0], cbp[0], fmaf(op[1], cbp[3], fmaf(op[2], cbp[6], dx)));
    dy = fmaf(op[0], cbp[1], fmaf(op[1], cbp[4], fmaf(op[2], cbp[7], dy)));
    dz = fmaf(op[0], cbp[2], fmaf(op[1], cbp[5], fmaf(op[2], cbp[8], dz)));
    out[idx] = (mask[idx] > 0.0f)
             ? sqrtf(fmaf(dx, dx, fmaf(dy, dy, dz * dz))) : 0.0f;
}

extern "C" void kernel_launch(void* const* d_in, const int* in_sizes, int n_in,
                              void* d_out, int out_size)
{
    const float* positions = (const float*)d_in[0];
    const int*   neighbors = (const int*)  d_in[1];
    const float* mask      = (const float*)d_in[2];
    const float* cell      = (const float*)d_in[3];
    const float* offsets   = (const float*)d_in[4];
    float*       out       = (float*)d_out;

    const int B      = in_sizes[3] / 9;
    const int n_rows = in_sizes[0] / 3;      // B*N
    const int N      = n_rows / B;
    const int K      = in_sizes[1] / n_rows;

    const size_t tabBytes = (size_t)N * 3 * sizeof(float);   // 48KB @ N=4096

    if (tabBytes <= 49152 && (K % 4) == 0) {
        static bool attr_set = false;
        if (!attr_set) {
            cudaFuncSetAttribute(pairwise_soa_kernel,
                                 cudaFuncAttributeMaxDynamicSharedMemorySize, 49152);
            attr_set = true;
        }
        // 2 CTAs/SM x 148 SMs = 296 slots; S segments per batch.
        int S = 296 / B; if (S < 1) S = 1;
        const int rowsPer = (N + S - 1) / S;
        S = (N + rowsPer - 1) / rowsPer;     // trim empty CTAs
        dim3 grid(S, B);
        pairwise_soa_kernel<<<grid, 512, tabBytes>>>(positions, neighbors, mask,
                                                     cell, offsets, out,
                                                     N, K, rowsPer);
    } else {
        const long total = (long)n_rows * K;
        const int grid = (int)((total + 255) / 256);
        pairwise_fallback_kernel<<<grid, 256>>>(positions, neighbors, mask,
                                                cell, offsets, out, N, K, total);
    }
}

// round 12
// speedup vs baseline: 1.0543x; 1.0543x over previous
#include <cuda_runtime.h>
#include <cuda_bf16.h>
#include <cstdint>

// PairwiseRepresentation: masked periodic pairwise distances.
//   positions      [B,N,3]   f32
//   neighbors      [B,N,K]   i32
//   neighbor_mask  [B,N,K]   f32
//   cell           [B,3,3]   f32
//   cell_offsets   [B,N,K,3] f32
//   out            [B,N,K]   f32
//
// R12: latency-exposure attack. 384 thr x 2 CTAs/SM (reg cap 85 -> no spills)
// with a software-pipelined K==128 row loop: next row's 5 streaming LDGs are
// issued before the current row is consumed (2x outstanding loads per warp),
// and the first row's loads are issued BEFORE __syncthreads so the table-fill
// barrier hides them. Table stays packed SoA (xy float2 + z float, 48KB).

// ---------------- main kernel ----------------
__global__ __launch_bounds__(384, 2)
void pairwise_soa_kernel(const float*  __restrict__ positions,
                         const int*    __restrict__ neighbors,
                         const float*  __restrict__ mask,
                         const float*  __restrict__ cell,
                         const float*  __restrict__ offsets,
                         float*        __restrict__ out,
                         int N, int K, int rowsPer)
{
    extern __shared__ float s_raw[];
    float2* sxy = (float2*)s_raw;        // N float2 (xy)
    float*  sz  = s_raw + 2 * N;         // N floats (z)

    const int b = blockIdx.y;

    // Division-free fill: 4 rows = 3 LDG.128 -> 3 STS.128.
    {
        const float4* pb4 = (const float4*)(positions + (size_t)b * N * 3);
        const int nGroups = N >> 2;            // fast path requires N % 4 == 0
        for (int g = threadIdx.x; g < nGroups; g += blockDim.x) {
            const float4 v0 = __ldg(&pb4[3 * g + 0]);  // x0 y0 z0 x1
            const float4 v1 = __ldg(&pb4[3 * g + 1]);  // y1 z1 x2 y2
            const float4 v2 = __ldg(&pb4[3 * g + 2]);  // z2 x3 y3 z3
            *(float4*)(sxy + 4 * g)     = make_float4(v0.x, v0.y, v0.w, v1.x);
            *(float4*)(sxy + 4 * g + 2) = make_float4(v1.z, v1.w, v2.y, v2.z);
            *(float4*)(sz + 4 * g)      = make_float4(v0.z, v1.y, v2.x, v2.w);
        }
        for (int r = (nGroups << 2) + threadIdx.x; r < N; r += blockDim.x) {
            const float* p = positions + (size_t)b * N * 3 + (size_t)r * 3;
            sxy[r] = make_float2(__ldg(&p[0]), __ldg(&p[1]));
            sz[r]  = __ldg(&p[2]);
        }
    }

    // Per-batch cell matrix -> registers.
    const float* cbp = cell + b * 9;
    const float c00 = __ldg(&cbp[0]), c01 = __ldg(&cbp[1]), c02 = __ldg(&cbp[2]);
    const float c10 = __ldg(&cbp[3]), c11 = __ldg(&cbp[4]), c12 = __ldg(&cbp[5]);
    const float c20 = __ldg(&cbp[6]), c21 = __ldg(&cbp[7]), c22 = __ldg(&cbp[8]);

    const int warp    = threadIdx.x >> 5;      // 0..11
    const int lane    = threadIdx.x & 31;
    const int n_warps = blockDim.x >> 5;       // 12

    const int r0 = blockIdx.x * rowsPer;
    const int r1 = min(r0 + rowsPer, N);

    if (K == 128) {
        // -------- pipelined fast path --------
        int  r    = r0 + warp;
        long base = ((long)b * N + r) * 128 + lane * 4;
        const long rowStride = (long)n_warps * 128;

        // Prologue: issue first row's loads BEFORE the barrier (they don't
        // touch smem, so the fill barrier wait hides their latency).
        int4 nb4; float4 mk4, o0, o1, o2;
        if (r < r1) {
            nb4 = __ldcs((const int4*)  (neighbors + base));
            mk4 = __ldcs((const float4*)(mask      + base));
            const float* offp = offsets + base * 3;
            o0 = __ldcs((const float4*)(offp + 0));
            o1 = __ldcs((const float4*)(offp + 4));
            o2 = __ldcs((const float4*)(offp + 8));
        }

        __syncthreads();

        while (r < r1) {
            const int  rn    = r + n_warps;
            const long basen = base + rowStride;

            // Prefetch next row's streams before consuming current row.
            int4 nbn; float4 mkn, o0n, o1n, o2n;
            if (rn < r1) {
                nbn = __ldcs((const int4*)  (neighbors + basen));
                mkn = __ldcs((const float4*)(mask      + basen));
                const float* offp = offsets + basen * 3;
                o0n = __ldcs((const float4*)(offp + 0));
                o1n = __ldcs((const float4*)(offp + 4));
                o2n = __ldcs((const float4*)(offp + 8));
            }

            // Consume current row.
            const float2 pixy = sxy[r];
            const float  piz  = sz[r];

            const int   jj[4] = { nb4.x, nb4.y, nb4.z, nb4.w };
            const float ox[4] = { o0.x, o0.w, o1.z, o2.y };
            const float oy[4] = { o0.y, o1.x, o1.w, o2.z };
            const float oz[4] = { o0.z, o1.y, o2.x, o2.w };
            const float mm[4] = { mk4.x, mk4.y, mk4.z, mk4.w };

            float2 gxy[4];
            float  gz[4];
#pragma unroll
            for (int t = 0; t < 4; ++t) {
                gxy[t] = sxy[jj[t]];
                gz[t]  = sz[jj[t]];
            }

            float res[4];
#pragma unroll
            for (int t = 0; t < 4; ++t) {
                float dx = gxy[t].x - pixy.x;
                float dy = gxy[t].y - pixy.y;
                float dz = gz[t]    - piz;
                dx = fmaf(ox[t], c00, fmaf(oy[t], c10, fmaf(oz[t], c20, dx)));
                dy = fmaf(ox[t], c01, fmaf(oy[t], c11, fmaf(oz[t], c21, dy)));
                dz = fmaf(ox[t], c02, fmaf(oy[t], c12, fmaf(oz[t], c22, dz)));
                res[t] = (mm[t] > 0.0f)
                       ? sqrtf(fmaf(dx, dx, fmaf(dy, dy, dz * dz))) : 0.0f;
            }

            __stcs((float4*)(out + base),
                   make_float4(res[0], res[1], res[2], res[3]));

            // Rotate pipeline.
            nb4 = nbn; mk4 = mkn; o0 = o0n; o1 = o1n; o2 = o2n;
            r = rn; base = basen;
        }
        return;
    }

    // -------- generic K path --------
    __syncthreads();
    for (int r = r0 + warp; r < r1; r += n_warps) {
        const float2 pixy = sxy[r];
        const float  piz  = sz[r];
        for (int k0 = lane * 4; k0 < K; k0 += 128) {
            const long base = ((long)b * N + r) * (long)K + k0;
            const int4   nb4 = __ldcs((const int4*)  (neighbors + base));
            const float4 mk4 = __ldcs((const float4*)(mask      + base));
            const float* offp = offsets + base * 3;
            const float4 o0 = __ldcs((const float4*)(offp + 0));
            const float4 o1 = __ldcs((const float4*)(offp + 4));
            const float4 o2 = __ldcs((const float4*)(offp + 8));
            const int   jj[4] = { nb4.x, nb4.y, nb4.z, nb4.w };
            const float ox[4] = { o0.x, o0.w, o1.z, o2.y };
            const float oy[4] = { o0.y, o1.x, o1.w, o2.z };
            const float oz[4] = { o0.z, o1.y, o2.x, o2.w };
            const float mm[4] = { mk4.x, mk4.y, mk4.z, mk4.w };
            float2 gxy[4]; float gz[4];
#pragma unroll
            for (int t = 0; t < 4; ++t) { gxy[t] = sxy[jj[t]]; gz[t] = sz[jj[t]]; }
            float res[4];
#pragma unroll
            for (int t = 0; t < 4; ++t) {
                float dx = gxy[t].x - pixy.x;
                float dy = gxy[t].y - pixy.y;
                float dz = gz[t]    - piz;
                dx = fmaf(ox[t], c00, fmaf(oy[t], c10, fmaf(oz[t], c20, dx)));
                dy = fmaf(ox[t], c01, fmaf(oy[t], c11, fmaf(oz[t], c21, dy)));
                dz = fmaf(ox[t], c02, fmaf(oy[t], c12, fmaf(oz[t], c22, dz)));
                res[t] = (mm[t] > 0.0f)
                       ? sqrtf(fmaf(dx, dx, fmaf(dy, dy, dz * dz))) : 0.0f;
            }
            __stcs((float4*)(out + base),
                   make_float4(res[0], res[1], res[2], res[3]));
        }
    }
}

// ---------------- scalar fallback (oversized N or K%4 != 0) ----------------
__global__ __launch_bounds__(256)
void pairwise_fallback_kernel(const float* __restrict__ positions,
                              const int*   __restrict__ neighbors,
                              const float* __restrict__ mask,
                              const float* __restrict__ cell,
                              const float* __restrict__ offsets,
                              float*       __restrict__ out,
                              int N, int K, long total)
{
    long idx = (long)blockIdx.x * blockDim.x + threadIdx.x;
    if (idx >= total) return;
    const long row = idx / K;
    const int  b   = (int)(row / N);

    const float pix = positions[row * 3 + 0];
    const float piy = positions[row * 3 + 1];
    const float piz = positions[row * 3 + 2];
    const int j = neighbors[idx];
    const float* pj  = positions + ((size_t)b * N + j) * 3;
    const float* cbp = cell + b * 9;
    const float* op  = offsets + idx * 3;
    float dx = pj[0] - pix, dy = pj[1] - piy, dz = pj[2] - piz;
    dx = fmaf(op[0], cbp[0], fmaf(op[1], cbp[3], fmaf(op[2], cbp[6], dx)));
    dy = fmaf(op[0], cbp[1], fmaf(op[1], cbp[4], fmaf(op[2], cbp[7], dy)));
    dz = fmaf(op[0], cbp[2], fmaf(op[1], cbp[5], fmaf(op[2], cbp[8], dz)));
    out[idx] = (mask[idx] > 0.0f)
             ? sqrtf(fmaf(dx, dx, fmaf(dy, dy, dz * dz))) : 0.0f;
}

extern "C" void kernel_launch(void* const* d_in, const int* in_sizes, int n_in,
                              void* d_out, int out_size)
{
    const float* positions = (const float*)d_in[0];
    const int*   neighbors = (const int*)  d_in[1];
    const float* mask      = (const float*)d_in[2];
    const float* cell      = (const float*)d_in[3];
    const float* offsets   = (const float*)d_in[4];
    float*       out       = (float*)d_out;

    const int B      = in_sizes[3] / 9;
    const int n_rows = in_sizes[0] / 3;      // B*N
    const int N      = n_rows / B;
    const int K      = in_sizes[1] / n_rows;

    const size_t tabBytes = (size_t)N * 3 * sizeof(float);   // 48KB @ N=4096

    if (tabBytes <= 49152 && (K % 4) == 0) {
        static bool attr_set = false;
        if (!attr_set) {
            cudaFuncSetAttribute(pairwise_soa_kernel,
                                 cudaFuncAttributeMaxDynamicSharedMemorySize, 49152);
            attr_set = true;
        }
        // 2 CTAs/SM x 148 SMs = 296 slots; S segments per batch.
        int S = 296 / B; if (S < 1) S = 1;
        const int rowsPer = (N + S - 1) / S;
        S = (N + rowsPer - 1) / rowsPer;     // trim empty CTAs
        dim3 grid(S, B);
        pairwise_soa_kernel<<<grid, 384, tabBytes>>>(positions, neighbors, mask,
                                                     cell, offsets, out,
                                                     N, K, rowsPer);
    } else {
        const long total = (long)n_rows * K;
        const int grid = (int)((total + 255) / 256);
        pairwise_fallback_kernel<<<grid, 256>>>(positions, neighbors, mask,
                                                cell, offsets, out, N, K, total);
    }
}

// round 13
// speedup vs baseline: 1.0563x; 1.0018x over previous
#include <cuda_runtime.h>
#include <cuda_bf16.h>
#include <cstdint>

// PairwiseRepresentation: masked periodic pairwise distances.
//   positions      [B,N,3]   f32
//   neighbors      [B,N,K]   i32
//   neighbor_mask  [B,N,K]   f32
//   cell           [B,3,3]   f32
//   cell_offsets   [B,N,K,3] f32
//   out            [B,N,K]   f32
//
// R13: R12's software-pipelined body (confirmed win: outstanding-loads/SM is
// the control variable) at 448 threads x 2 CTAs/SM: 28 warps/SM (+17% vs 384)
// with reg cap 73 — a 5-reg squeeze from R12's 78, small enough to avoid
// spills. 28 warps x 10 outstanding LDGs = 280 in flight/SM (was 240).

// ---------------- main kernel ----------------
__global__ __launch_bounds__(448, 2)
void pairwise_soa_kernel(const float*  __restrict__ positions,
                         const int*    __restrict__ neighbors,
                         const float*  __restrict__ mask,
                         const float*  __restrict__ cell,
                         const float*  __restrict__ offsets,
                         float*        __restrict__ out,
                         int N, int K, int rowsPer)
{
    extern __shared__ float s_raw[];
    float2* sxy = (float2*)s_raw;        // N float2 (xy)
    float*  sz  = s_raw + 2 * N;         // N floats (z)

    const int b = blockIdx.y;

    // Division-free fill: 4 rows = 3 LDG.128 -> 3 STS.128.
    {
        const float4* pb4 = (const float4*)(positions + (size_t)b * N * 3);
        const int nGroups = N >> 2;            // fast path requires N % 4 == 0
        for (int g = threadIdx.x; g < nGroups; g += blockDim.x) {
            const float4 v0 = __ldg(&pb4[3 * g + 0]);  // x0 y0 z0 x1
            const float4 v1 = __ldg(&pb4[3 * g + 1]);  // y1 z1 x2 y2
            const float4 v2 = __ldg(&pb4[3 * g + 2]);  // z2 x3 y3 z3
            *(float4*)(sxy + 4 * g)     = make_float4(v0.x, v0.y, v0.w, v1.x);
            *(float4*)(sxy + 4 * g + 2) = make_float4(v1.z, v1.w, v2.y, v2.z);
            *(float4*)(sz + 4 * g)      = make_float4(v0.z, v1.y, v2.x, v2.w);
        }
        for (int r = (nGroups << 2) + threadIdx.x; r < N; r += blockDim.x) {
            const float* p = positions + (size_t)b * N * 3 + (size_t)r * 3;
            sxy[r] = make_float2(__ldg(&p[0]), __ldg(&p[1]));
            sz[r]  = __ldg(&p[2]);
        }
    }

    // Per-batch cell matrix -> registers.
    const float* cbp = cell + b * 9;
    const float c00 = __ldg(&cbp[0]), c01 = __ldg(&cbp[1]), c02 = __ldg(&cbp[2]);
    const float c10 = __ldg(&cbp[3]), c11 = __ldg(&cbp[4]), c12 = __ldg(&cbp[5]);
    const float c20 = __ldg(&cbp[6]), c21 = __ldg(&cbp[7]), c22 = __ldg(&cbp[8]);

    const int warp    = threadIdx.x >> 5;      // 0..13
    const int lane    = threadIdx.x & 31;
    const int n_warps = blockDim.x >> 5;       // 14

    const int r0 = blockIdx.x * rowsPer;
    const int r1 = min(r0 + rowsPer, N);

    if (K == 128) {
        // -------- pipelined fast path --------
        int  r    = r0 + warp;
        long base = ((long)b * N + r) * 128 + lane * 4;
        const long rowStride = (long)n_warps * 128;

        // Prologue: first row's loads issued BEFORE the barrier (they don't
        // touch smem, so the fill barrier wait hides their latency).
        int4 nb4; float4 mk4, o0, o1, o2;
        if (r < r1) {
            nb4 = __ldcs((const int4*)  (neighbors + base));
            mk4 = __ldcs((const float4*)(mask      + base));
            const float* offp = offsets + base * 3;
            o0 = __ldcs((const float4*)(offp + 0));
            o1 = __ldcs((const float4*)(offp + 4));
            o2 = __ldcs((const float4*)(offp + 8));
        }

        __syncthreads();

        while (r < r1) {
            const int  rn    = r + n_warps;
            const long basen = base + rowStride;

            // Prefetch next row's streams before consuming current row.
            int4 nbn; float4 mkn, o0n, o1n, o2n;
            if (rn < r1) {
                nbn = __ldcs((const int4*)  (neighbors + basen));
                mkn = __ldcs((const float4*)(mask      + basen));
                const float* offp = offsets + basen * 3;
                o0n = __ldcs((const float4*)(offp + 0));
                o1n = __ldcs((const float4*)(offp + 4));
                o2n = __ldcs((const float4*)(offp + 8));
            }

            // Consume current row.
            const float2 pixy = sxy[r];
            const float  piz  = sz[r];

            const int   jj[4] = { nb4.x, nb4.y, nb4.z, nb4.w };
            const float ox[4] = { o0.x, o0.w, o1.z, o2.y };
            const float oy[4] = { o0.y, o1.x, o1.w, o2.z };
            const float oz[4] = { o0.z, o1.y, o2.x, o2.w };
            const float mm[4] = { mk4.x, mk4.y, mk4.z, mk4.w };

            float2 gxy[4];
            float  gz[4];
#pragma unroll
            for (int t = 0; t < 4; ++t) {
                gxy[t] = sxy[jj[t]];
                gz[t]  = sz[jj[t]];
            }

            float res[4];
#pragma unroll
            for (int t = 0; t < 4; ++t) {
                float dx = gxy[t].x - pixy.x;
                float dy = gxy[t].y - pixy.y;
                float dz = gz[t]    - piz;
                dx = fmaf(ox[t], c00, fmaf(oy[t], c10, fmaf(oz[t], c20, dx)));
                dy = fmaf(ox[t], c01, fmaf(oy[t], c11, fmaf(oz[t], c21, dy)));
                dz = fmaf(ox[t], c02, fmaf(oy[t], c12, fmaf(oz[t], c22, dz)));
                res[t] = (mm[t] > 0.0f)
                       ? sqrtf(fmaf(dx, dx, fmaf(dy, dy, dz * dz))) : 0.0f;
            }

            __stcs((float4*)(out + base),
                   make_float4(res[0], res[1], res[2], res[3]));

            // Rotate pipeline.
            nb4 = nbn; mk4 = mkn; o0 = o0n; o1 = o1n; o2 = o2n;
            r = rn; base = basen;
        }
        return;
    }

    // -------- generic K path --------
    __syncthreads();
    for (int r = r0 + warp; r < r1; r += n_warps) {
        const float2 pixy = sxy[r];
        const float  piz  = sz[r];
        for (int k0 = lane * 4; k0 < K; k0 += 128) {
            const long base = ((long)b * N + r) * (long)K + k0;
            const int4   nb4 = __ldcs((const int4*)  (neighbors + base));
            const float4 mk4 = __ldcs((const float4*)(mask      + base));
            const float* offp = offsets + base * 3;
            const float4 o0 = __ldcs((const float4*)(offp + 0));
            const float4 o1 = __ldcs((const float4*)(offp + 4));
            const float4 o2 = __ldcs((const float4*)(offp + 8));
            const int   jj[4] = { nb4.x, nb4.y, nb4.z, nb4.w };
            const float ox[4] = { o0.x, o0.w, o1.z, o2.y };
            const float oy[4] = { o0.y, o1.x, o1.w, o2.z };
            const float oz[4] = { o0.z, o1.y, o2.x, o2.w };
            const float mm[4] = { mk4.x, mk4.y, mk4.z, mk4.w };
            float2 gxy[4]; float gz[4];
#pragma unroll
            for (int t = 0; t < 4; ++t) { gxy[t] = sxy[jj[t]]; gz[t] = sz[jj[t]]; }
            float res[4];
#pragma unroll
            for (int t = 0; t < 4; ++t) {
                float dx = gxy[t].x - pixy.x;
                float dy = gxy[t].y - pixy.y;
                float dz = gz[t]    - piz;
                dx = fmaf(ox[t], c00, fmaf(oy[t], c10, fmaf(oz[t], c20, dx)));
                dy = fmaf(ox[t], c01, fmaf(oy[t], c11, fmaf(oz[t], c21, dy)));
                dz = fmaf(ox[t], c02, fmaf(oy[t], c12, fmaf(oz[t], c22, dz)));
                res[t] = (mm[t] > 0.0f)
                       ? sqrtf(fmaf(dx, dx, fmaf(dy, dy, dz * dz))) : 0.0f;
            }
            __stcs((float4*)(out + base),
                   make_float4(res[0], res[1], res[2], res[3]));
        }
    }
}

// ---------------- scalar fallback (oversized N or K%4 != 0) ----------------
__global__ __launch_bounds__(256)
void pairwise_fallback_kernel(const float* __restrict__ positions,
                              const int*   __restrict__ neighbors,
                              const float* __restrict__ mask,
                              const float* __restrict__ cell,
                              const float* __restrict__ offsets,
                              float*       __restrict__ out,
                              int N, int K, long total)
{
    long idx = (long)blockIdx.x * blockDim.x + threadIdx.x;
    if (idx >= total) return;
    const long row = idx / K;
    const int  b   = (int)(row / N);

    const float pix = positions[row * 3 + 0];
    const float piy = positions[row * 3 + 1];
    const float piz = positions[row * 3 + 2];
    const int j = neighbors[idx];
    const float* pj  = positions + ((size_t)b * N + j) * 3;
    const float* cbp = cell + b * 9;
    const float* op  = offsets + idx * 3;
    float dx = pj[0] - pix, dy = pj[1] - piy, dz = pj[2] - piz;
    dx = fmaf(op[0], cbp[0], fmaf(op[1], cbp[3], fmaf(op[2], cbp[6], dx)));
    dy = fmaf(op[0], cbp[1], fmaf(op[1], cbp[4], fmaf(op[2], cbp[7], dy)));
    dz = fmaf(op[0], cbp[2], fmaf(op[1], cbp[5], fmaf(op[2], cbp[8], dz)));
    out[idx] = (mask[idx] > 0.0f)
             ? sqrtf(fmaf(dx, dx, fmaf(dy, dy, dz * dz))) : 0.0f;
}

extern "C" void kernel_launch(void* const* d_in, const int* in_sizes, int n_in,
                              void* d_out, int out_size)
{
    const float* positions = (const float*)d_in[0];
    const int*   neighbors = (const int*)  d_in[1];
    const float* mask      = (const float*)d_in[2];
    const float* cell      = (const float*)d_in[3];
    const float* offsets   = (const float*)d_in[4];
    float*       out       = (float*)d_out;

    const int B      = in_sizes[3] / 9;
    const int n_rows = in_sizes[0] / 3;      // B*N
    const int N      = n_rows / B;
    const int K      = in_sizes[1] / n_rows;

    const size_t tabBytes = (size_t)N * 3 * sizeof(float);   // 48KB @ N=4096

    if (tabBytes <= 49152 && (K % 4) == 0) {
        static bool attr_set = false;
        if (!attr_set) {
            cudaFuncSetAttribute(pairwise_soa_kernel,
                                 cudaFuncAttributeMaxDynamicSharedMemorySize, 49152);
            attr_set = true;
        }
        // 2 CTAs/SM x 148 SMs = 296 slots; S segments per batch.
        int S = 296 / B; if (S < 1) S = 1;
        const int rowsPer = (N + S - 1) / S;
        S = (N + rowsPer - 1) / rowsPer;     // trim empty CTAs
        dim3 grid(S, B);
        pairwise_soa_kernel<<<grid, 448, tabBytes>>>(positions, neighbors, mask,
                                                     cell, offsets, out,
                                                     N, K, rowsPer);
    } else {
        const long total = (long)n_rows * K;
        const int grid = (int)((total + 255) / 256);
        pairwise_fallback_kernel<<<grid, 256>>>(positions, neighbors, mask,
                                                cell, offsets, out, N, K, total);
    }
}